// round 9
// baseline (speedup 1.0000x reference)
#include <cuda_runtime.h>
#include <math.h>

#define TT 512
#define BB 32
#define II 512
#define HH 1024
#define BH (BB*HH)
#define TBH (TT*BB*HH)
#define NBLK 128

__device__ float g_P[(size_t)4 * TBH];
__device__ float g_h[BH];
__device__ float g_c[2][BH];
__device__ float g_po[BH];
__device__ float g_bias[4][HH];
__device__ float g_Wpk[(size_t)448 * 16384];      // 384 phase1 tiles + 64 Wcyo tiles
__device__ float g_WpkI[(size_t)4 * 64 * 8192];   // input weights, frag-packed
__device__ __align__(16) unsigned g_fB[128];
__device__ __align__(16) unsigned g_fC[128];
__device__ volatile unsigned g_genB;
__device__ volatile unsigned g_genC;

__device__ __forceinline__ unsigned cvt_tf32(float x) {
    unsigned r; asm("cvt.rna.tf32.f32 %0, %1;" : "=r"(r) : "f"(x)); return r;
}
__device__ __forceinline__ void st4tf(float* p, float4 v) {
    uint4 u; u.x = cvt_tf32(v.x); u.y = cvt_tf32(v.y);
    u.z = cvt_tf32(v.z); u.w = cvt_tf32(v.w); *(uint4*)p = u;
}
__device__ __forceinline__ void mma_tf32(float* d, uint4 a, unsigned b0, unsigned b1) {
    asm("mma.sync.aligned.m16n8k8.row.col.f32.tf32.tf32.f32 "
        "{%0,%1,%2,%3},{%4,%5,%6,%7},{%8,%9},{%0,%1,%2,%3};"
        : "+f"(d[0]), "+f"(d[1]), "+f"(d[2]), "+f"(d[3])
        : "r"(a.x), "r"(a.y), "r"(a.z), "r"(a.w), "r"(b0), "r"(b1));
}

__device__ __forceinline__ void bar_arrive(unsigned* f, int bId, unsigned v) {
    __syncthreads();
    if (threadIdx.x == 0) {
        __threadfence();
        asm volatile("st.relaxed.gpu.global.u32 [%0], %1;"
                     :: "l"(f + bId), "r"(v) : "memory");
    }
}
__device__ __forceinline__ void bar_master(const unsigned* f, int n, unsigned v,
                                           volatile unsigned* gen) {
    if (threadIdx.x < 32) {
        int i = threadIdx.x * 4;
        bool act = i < n;
        const unsigned* p = f + i;
        for (;;) {
            unsigned x0 = v, x1 = v, x2 = v, x3 = v;
            if (act)
                asm volatile("ld.relaxed.gpu.global.v4.u32 {%0,%1,%2,%3},[%4];"
                             : "=r"(x0), "=r"(x1), "=r"(x2), "=r"(x3) : "l"(p));
            bool ok = (x0 >= v) && (x1 >= v) && (x2 >= v) && (x3 >= v);
            if (__all_sync(0xffffffffu, ok)) break;
        }
        __threadfence();
        if (threadIdx.x == 0) *gen = v;
    }
    __syncthreads();
}
__device__ __forceinline__ void bar_spin(volatile unsigned* gen, unsigned v) {
    if (threadIdx.x == 0) {
        while (*gen < v) { }
        __threadfence();
    }
    __syncthreads();
}

__global__ void __launch_bounds__(256) init_kernel(
    const float* __restrict__ h0, const float* __restrict__ c0,
    const float* __restrict__ b_ii, const float* __restrict__ b_hi,
    const float* __restrict__ b_ci, const float* __restrict__ b_if,
    const float* __restrict__ b_hf, const float* __restrict__ b_cf,
    const float* __restrict__ b_ic, const float* __restrict__ b_hc,
    const float* __restrict__ b_io, const float* __restrict__ b_ho,
    const float* __restrict__ b_cyo)
{
    int i = blockIdx.x * blockDim.x + threadIdx.x;
    if (i < BH) { g_h[i] = h0[i]; g_c[0][i] = c0[i]; }
    if (i < HH) {
        g_bias[0][i] = b_ii[i] + b_hi[i] + b_ci[i];
        g_bias[1][i] = b_if[i] + b_hf[i] + b_cf[i];
        g_bias[2][i] = b_ic[i] + b_hc[i];
        g_bias[3][i] = b_io[i] + b_ho[i] + b_cyo[i];
    }
    if (i < 128) { g_fB[i] = 0; g_fC[i] = 0; }
    if (i == 0) { g_genB = 0; g_genC = 0; }
}

// Pack weights into m16n8k8 A-fragment order (same layout as R8).
__global__ void __launch_bounds__(256) pack_kernel(
    const float* __restrict__ w0, const float* __restrict__ w1,
    const float* __restrict__ w2, const float* __restrict__ w3,
    const float* __restrict__ w4, const float* __restrict__ w5,
    const float* __restrict__ w6)
{
    int gid = blockIdx.x * 256 + threadIdx.x;
    int s = gid >> 14, rem = gid & 16383;
    int kt = rem >> 7, lane = (rem >> 2) & 31, jj = rem & 3;
    int kcol = kt * 8 + (lane & 3) + 4 * (jj >> 1);
    float v;
    if (s < 384) {
        int bId = s / 3, tt = s - 3 * bId;
        int r = (lane >> 2) + 8 * (jj & 1);
        int mat = tt * 2 + (r >> 3);
        int n = bId * 8 + (r & 7);
        const float* W = (mat == 0) ? w0 : (mat == 1) ? w1 : (mat == 2) ? w2 :
                         (mat == 3) ? w3 : (mat == 4) ? w4 : w5;
        v = __ldg(&W[n * HH + kcol]);
    } else {
        int ng = s - 384;
        int row = ng * 16 + (lane >> 2) + 8 * (jj & 1);
        v = __ldg(&w6[row * HH + kcol]);
    }
    g_Wpk[gid] = __uint_as_float(cvt_tf32(v));
}

__global__ void __launch_bounds__(256) pack_in_kernel(
    const float* __restrict__ w0, const float* __restrict__ w1,
    const float* __restrict__ w2, const float* __restrict__ w3)
{
    int gid = blockIdx.x * 256 + threadIdx.x;
    int mat = gid >> 19, rem = gid & 524287;
    int ng = rem >> 13, kt = (rem >> 7) & 63, lane = (rem >> 2) & 31, jj = rem & 3;
    int row = ng * 16 + (lane >> 2) + 8 * (jj & 1);
    int col = kt * 8 + (lane & 3) + 4 * (jj >> 1);
    const float* W = (mat == 0) ? w0 : (mat == 1) ? w1 : (mat == 2) ? w2 : w3;
    g_WpkI[gid] = __uint_as_float(cvt_tf32(__ldg(&W[row * II + col])));
}

// proj (tf32 mma): unchanged from R8
#define PROJ_SMEM (32768 + 2*2176 + 2176 + 64)
__global__ void __launch_bounds__(256) proj2_kernel(const float* __restrict__ X)
{
    extern __shared__ float smem[];
    float* sA = smem;
    float* sX = smem + 32768;
    float* sT = smem + 32768 + 4352;
    float* sBias = sT + 2176;

    const int tid = threadIdx.x;
    const int bn = blockIdx.x & 63, bm = blockIdx.x >> 6;
    const int w = tid >> 5, lane = tid & 31;
    const int ta = w >> 1, mh = w & 1;

    {
        const float4* src = (const float4*)(g_WpkI + (size_t)(bn * 4) * 8192);
        float4* dst = (float4*)sA;
        for (int p = tid; p < 8192; p += 256) dst[p] = __ldg(src + p);
    }
    if (tid < 64) {
        int np = bn * 64 + tid;
        sBias[tid] = g_bias[np >> 10][np & 1023];
    }

    const int v1 = tid + 256;
    const int b0s = tid >> 4, kq0 = (tid & 15) * 4;
    const int b1s = v1 >> 4,  kq1 = (v1 & 15) * 4;
    const int brow0 = (mh * 16 + (lane >> 2)) * 68 + (lane & 3);
    const int brow1 = (mh * 16 + 8 + (lane >> 2)) * 68 + (lane & 3);

    const float* tilebase = sA + ta * 8192;
    const int gate = (bn * 64) >> 10;
    const int nbase = (bn * 64) & 1023;
    __syncthreads();

    for (int mc = 0; mc < 256; mc++) {
        const int m0 = bm * 8192 + mc * 32;

        float acc[2][4];
#pragma unroll
        for (int g = 0; g < 2; g++)
#pragma unroll
            for (int j = 0; j < 4; j++) acc[g][j] = 0.f;

        float4 px0 = __ldg((const float4*)(X + (size_t)(m0 + b0s) * II + kq0));
        float4 px1 = __ldg((const float4*)(X + (size_t)(m0 + b1s) * II + kq1));

        for (int j = 0; j < 8; j++) {
            float* xb = sX + (j & 1) * 2176;
            __syncthreads();
            st4tf(xb + b0s * 68 + kq0, px0);
            st4tf(xb + b1s * 68 + kq1, px1);
            __syncthreads();
            if (j < 7) {
                int k1 = (j + 1) * 64;
                px0 = __ldg((const float4*)(X + (size_t)(m0 + b0s) * II + k1 + kq0));
                px1 = __ldg((const float4*)(X + (size_t)(m0 + b1s) * II + k1 + kq1));
            }
#pragma unroll
            for (int kt = 0; kt < 8; kt++) {
                const int colo = kt * 8;
                unsigned x0a = *(const unsigned*)(xb + brow0 + colo);
                unsigned x1a = *(const unsigned*)(xb + brow0 + colo + 4);
                unsigned x0b = *(const unsigned*)(xb + brow1 + colo);
                unsigned x1b = *(const unsigned*)(xb + brow1 + colo + 4);
                uint4 a = *(const uint4*)(tilebase + (j * 8 + kt) * 128 + lane * 4);
                mma_tf32(acc[0], a, x0a, x1a);
                mma_tf32(acc[1], a, x0b, x1b);
            }
        }

        __syncthreads();
#pragma unroll
        for (int g = 0; g < 2; g++)
#pragma unroll
            for (int j = 0; j < 4; j++) {
                int nrow = ta * 16 + (lane >> 2) + 8 * (j >> 1);
                int mcol = mh * 16 + g * 8 + 2 * (lane & 3) + (j & 1);
                sT[mcol * 68 + nrow] = acc[g][j];
            }
        __syncthreads();
#pragma unroll
        for (int e = 0; e < 2; e++) {
            int idx = tid + e * 256;
            int row = idx >> 4, q = idx & 15;
            float4 v = *(float4*)(sT + row * 68 + q * 4);
            v.x += sBias[q * 4 + 0]; v.y += sBias[q * 4 + 1];
            v.z += sBias[q * 4 + 2]; v.w += sBias[q * 4 + 3];
            *(float4*)(g_P + (size_t)gate * TBH + (size_t)(m0 + row) * HH + nbase + q * 4) = v;
        }
    }
}

// persistent tf32 recurrence: peephole MMAs fused into phase 2's cy staging.
#define SMEM_FLOATS (49152 + 8704)
extern "C" __global__ void __launch_bounds__(256) lstm_kernel(float* __restrict__ out)
{
    extern __shared__ float smem[];
    float* sW  = smem;              // 3 tiles x 16384
    float* sB  = smem + 49152;      // staging + reduction (8704 floats)

    const int tid = threadIdx.x, bId = blockIdx.x;
    const int w = tid >> 5, lane = tid & 31;
    const int kw = w >> 1, bgset = w & 1;

    const int s0 = 3 * bId;
#pragma unroll
    for (int tt = 0; tt < 3; tt++) {
        const float4* src = (const float4*)(g_Wpk + (size_t)(s0 + tt) * 16384);
        float4* dst = (float4*)(sW + tt * 16384);
        for (int p = tid; p < 4096; p += 256) dst[p] = __ldg(src + p);
    }

    // ---- phase-1 (h-only, 128-k chunks) roles ----
    const int r1 = tid >> 3;               // 0..31 (batch row)
    const int cb1 = (tid & 7) * 16;        // col group base
    const int brow0_1 = (bgset * 16 + (lane >> 2)) * 132 + (lane & 3);
    const int brow1_1 = brow0_1 + 8 * 132;
    float* sH1 = sB;                       // 2 bufs x 4224 (32x132)

    // ---- phase-2 / peephole (64-k chunks, 32 cy rows) roles ----
    const int v1 = tid + 256;
    const int b0s = tid >> 4, kq0 = (tid & 15) * 4;
    const int b1s = v1 >> 4,  kq1 = (v1 & 15) * 4;
    const int brow0_2 = (bgset * 16 + (lane >> 2)) * 68 + (lane & 3);
    const int brow1_2 = brow0_2 + 8 * 68;
    float* sCy = sB;                       // 2 bufs x 2176 (32x68)
    float* sA2 = sB + 4352;                // 2 bufs x 1088
    const int half = bId >> 6, ng = bId & 63;
    const float* wsrc2 = g_Wpk + (size_t)(384 + ng) * 16384;
    const int ph0 = (half * 16 + (lane >> 2)) * 68 + (lane & 3);
    const int ph1 = ph0 + 8 * 68;
    float* sRedW = sB;                     // 1792 (after loop, buf0 free)
    float* sRedC = sB + 2048;              // 1536 (after loop, buf1 free)

    // pointwise ownership (warps 0,1): col nl, 4 (g,jb) batch slots
    const int nl = lane >> 2;
    const int nown = bId * 8 + nl;
    int offs[4];
#pragma unroll
    for (int gj = 0; gj < 4; gj++) {
        int g = gj >> 1, jb = gj & 1;
        int bcol = bgset * 16 + g * 8 + 2 * (lane & 3) + jb;
        offs[gj] = bcol * HH + nown;
    }

    __syncthreads();

    // ---- pre-pass: peephole partials from c0 (tile 2 x c0) ----
    float accC[2][4];
#pragma unroll
    for (int g = 0; g < 2; g++)
#pragma unroll
        for (int j = 0; j < 4; j++) accC[g][j] = 0.f;
    {
        const float* c0p = g_c[0];
        float accp[2][4];
#pragma unroll
        for (int g = 0; g < 2; g++)
#pragma unroll
            for (int j = 0; j < 4; j++) accp[g][j] = 0.f;
        for (int j = 0; j < 16; j++) {
            __syncthreads();
            st4tf(sCy + b0s * 68 + kq0,
                  __ldcg((const float4*)(c0p + b0s * HH + j * 64 + kq0)));
            st4tf(sCy + b1s * 68 + kq1,
                  __ldcg((const float4*)(c0p + b1s * HH + j * 64 + kq1)));
            __syncthreads();
#pragma unroll
            for (int q = 0; q < 2; q++) {
                const int kt = kw * 2 + q, colo = kt * 8;
                unsigned c0a = *(const unsigned*)(sCy + brow0_2 + colo);
                unsigned c1a = *(const unsigned*)(sCy + brow0_2 + colo + 4);
                unsigned c0b = *(const unsigned*)(sCy + brow1_2 + colo);
                unsigned c1b = *(const unsigned*)(sCy + brow1_2 + colo + 4);
                uint4 a2 = *(const uint4*)(sW + 32768 + (j * 8 + kt) * 128 + lane * 4);
                mma_tf32(accp[0], a2, c0a, c1a);
                mma_tf32(accp[1], a2, c0b, c1b);
            }
        }
        __syncthreads();
        if (kw > 0) {
            float* dst = sRedC + (((kw - 1) * 2 + bgset) * 32 + lane) * 8;
#pragma unroll
            for (int g = 0; g < 2; g++)
#pragma unroll
                for (int j = 0; j < 4; j++) dst[g * 4 + j] = accp[g][j];
        }
        __syncthreads();
        if (kw == 0) {
#pragma unroll
            for (int g = 0; g < 2; g++)
#pragma unroll
                for (int j = 0; j < 4; j++) accC[g][j] = accp[g][j];
#pragma unroll
            for (int r = 0; r < 3; r++) {
                const float* sp = sRedC + ((r * 2 + bgset) * 32 + lane) * 8;
#pragma unroll
                for (int g = 0; g < 2; g++)
#pragma unroll
                    for (int j = 0; j < 4; j++) accC[g][j] += sp[g * 4 + j];
            }
        }
        __syncthreads();
    }

    for (int t = 0; t < TT; t++) {
        const int cur = t & 1, nxt = cur ^ 1;
        const float* c_in = g_c[cur];

        // prefetch pointwise operands (warps 0,1)
        float pP[4][4], pC[4];
        if (w < 2) {
#pragma unroll
            for (int gj = 0; gj < 4; gj++) {
                size_t pb = (size_t)t * BH + offs[gj];
                pP[0][gj] = __ldg(&g_P[pb]);
                pP[1][gj] = __ldg(&g_P[(size_t)TBH + pb]);
                pP[2][gj] = __ldg(&g_P[2 * (size_t)TBH + pb]);
                pP[3][gj] = __ldg(&g_P[3 * (size_t)TBH + pb]);
                pC[gj] = __ldcg(&c_in[offs[gj]]);
            }
        }

        // ---------- phase 1: tiles 0,1 x h (8 chunks of 128 k) ----------
        float acc[2][2][4];
#pragma unroll
        for (int a = 0; a < 2; a++)
#pragma unroll
            for (int g = 0; g < 2; g++)
#pragma unroll
                for (int j = 0; j < 4; j++) acc[a][g][j] = 0.f;

        float4 rh[4];
#pragma unroll
        for (int i = 0; i < 4; i++)
            rh[i] = __ldcg((const float4*)(g_h + r1 * HH + cb1 + i * 4));
#pragma unroll
        for (int i = 0; i < 4; i++)
            st4tf(sH1 + r1 * 132 + cb1 + i * 4, rh[i]);
#pragma unroll
        for (int i = 0; i < 4; i++)
            rh[i] = __ldcg((const float4*)(g_h + r1 * HH + 128 + cb1 + i * 4));
        __syncthreads();

        for (int j = 0; j < 8; j++) {
            float* bh = sH1 + (j & 1) * 4224;
            if (j < 7) {
                float* bn_ = sH1 + ((j + 1) & 1) * 4224;
#pragma unroll
                for (int i = 0; i < 4; i++)
                    st4tf(bn_ + r1 * 132 + cb1 + i * 4, rh[i]);
                if (j < 6) {
                    int k2 = (j + 2) * 128;
#pragma unroll
                    for (int i = 0; i < 4; i++)
                        rh[i] = __ldcg((const float4*)(g_h + r1 * HH + k2 + cb1 + i * 4));
                }
            }
#pragma unroll
            for (int q = 0; q < 4; q++) {
                const int kt = kw * 4 + q, colo = kt * 8;
                unsigned h0a = *(const unsigned*)(bh + brow0_1 + colo);
                unsigned h1a = *(const unsigned*)(bh + brow0_1 + colo + 4);
                unsigned h0b = *(const unsigned*)(bh + brow1_1 + colo);
                unsigned h1b = *(const unsigned*)(bh + brow1_1 + colo + 4);
                const int gkt = j * 16 + kt;
                uint4 a0 = *(const uint4*)(sW + gkt * 128 + lane * 4);
                uint4 a1 = *(const uint4*)(sW + 16384 + gkt * 128 + lane * 4);
                mma_tf32(acc[0][0], a0, h0a, h1a);
                mma_tf32(acc[0][1], a0, h0b, h1b);
                mma_tf32(acc[1][0], a1, h0a, h1a);
                mma_tf32(acc[1][1], a1, h0b, h1b);
            }
            __syncthreads();
        }

        // cross-k-split reduction (2 tiles); warps 0,1 hold totals
        if (kw > 0) {
            float* dst = sB + (((kw - 1) * 2 + bgset) * 32 + lane) * 16;
#pragma unroll
            for (int a = 0; a < 2; a++)
#pragma unroll
                for (int g = 0; g < 2; g++)
#pragma unroll
                    for (int j = 0; j < 4; j++) dst[a * 8 + g * 4 + j] = acc[a][g][j];
        }
        __syncthreads();
        if (kw == 0) {
#pragma unroll
            for (int r = 0; r < 3; r++) {
                const float* sp = sB + ((r * 2 + bgset) * 32 + lane) * 16;
#pragma unroll
                for (int a = 0; a < 2; a++)
#pragma unroll
                    for (int g = 0; g < 2; g++)
#pragma unroll
                        for (int j = 0; j < 4; j++) acc[a][g][j] += sp[a * 8 + g * 4 + j];
            }
            // local pointwise: gates, cy, po (uses carried peephole accC)
#pragma unroll
            for (int gj = 0; gj < 4; gj++) {
                int g = gj >> 1, jb = gj & 1;
                float hi = acc[0][g][jb],  hf = acc[0][g][2 + jb];
                float hc = acc[1][g][jb],  ho = acc[1][g][2 + jb];
                float ci = accC[g][jb],    cf = accC[g][2 + jb];
                float pi = pP[0][gj] + hi + ci;
                float pf = pP[1][gj] + hf + cf;
                float pg = pP[2][gj] + hc;
                float po = pP[3][gj] + ho;
                float iv = 1.f / (1.f + expf(-pi));
                float fv = 1.f / (1.f + expf(-pf));
                float gv = tanhf(pg);
                float cy = fmaf(fv, pC[gj], iv * gv);
                g_c[nxt][offs[gj]] = cy;
                g_po[offs[gj]] = po;
            }
        }
        // barrier B (cy/po published)
        bar_arrive(g_fB, bId, (unsigned)(t + 1));
        if (bId == 0) bar_master(g_fB, 128, (unsigned)(t + 1), &g_genB);
        else          bar_spin(&g_genB, (unsigned)(t + 1));

        // ---------- phase 2: Wcyo GEMM + next-step peephole, fused --------
        {
            const float* cyp = g_c[nxt];

            // epilogue operand prefetch (warp 0)
            float ppo[2][4], pcy[2][4];
            if (w == 0) {
#pragma unroll
                for (int g = 0; g < 2; g++)
#pragma unroll
                    for (int j = 0; j < 4; j++) {
                        int row = ng * 16 + (lane >> 2) + 8 * (j >> 1);
                        int bcol = half * 16 + g * 8 + 2 * (lane & 3) + (j & 1);
                        int off = bcol * HH + row;
                        ppo[g][j] = __ldcg(&g_po[off]);
                        pcy[g][j] = __ldcg(&cyp[off]);
                    }
            }

            float acc2[2][4], accp[2][4];
#pragma unroll
            for (int g = 0; g < 2; g++)
#pragma unroll
                for (int j = 0; j < 4; j++) { acc2[g][j] = 0.f; accp[g][j] = 0.f; }

            // prologue: stage chunk 0, prefetch chunk 1
            float4 ry0 = __ldcg((const float4*)(cyp + b0s * HH + kq0));
            float4 ry1 = __ldcg((const float4*)(cyp + b1s * HH + kq1));
            float4 ra  = __ldg((const float4*)wsrc2 + tid);
            st4tf(sCy + b0s * 68 + kq0, ry0);
            st4tf(sCy + b1s * 68 + kq1, ry1);
            *(float4*)(sA2 + tid * 4) = ra;
            ry0 = __ldcg((const float4*)(cyp + b0s * HH + 64 + kq0));
            ry1 = __ldcg((const float4*)(cyp + b1s * HH + 64 + kq1));
            ra  = __ldg((const float4*)(wsrc2 + 1024) + tid);
            __syncthreads();

            for (int j = 0; j < 16; j++) {
                float* cb = sCy + (j & 1) * 2176;
                float* ab = sA2 + (j & 1) * 1088;
                if (j < 15) {
                    float* cbn = sCy + ((j + 1) & 1) * 2176;
                    float* abn = sA2 + ((j + 1) & 1) * 1088;
                    st4tf(cbn + b0s * 68 + kq0, ry0);
                    st4tf(cbn + b1s * 68 + kq1, ry1);
                    *(float4*)(abn + tid * 4) = ra;
                    if (j < 14) {
                        int k2 = (j + 2) * 64;
                        ry0 = __ldcg((const float4*)(cyp + b0s * HH + k2 + kq0));
                        ry1 = __ldcg((const float4*)(cyp + b1s * HH + k2 + kq1));
                        ra  = __ldg((const float4*)(wsrc2 + (j + 2) * 1024) + tid);
                    }
                }
                // Wcyo part (8-way k-split over this chunk's 8 ktiles)
                {
                    const int colo = w * 8;
                    unsigned y0a = *(const unsigned*)(cb + ph0 + colo);
                    unsigned y1a = *(const unsigned*)(cb + ph0 + colo + 4);
                    unsigned y0b = *(const unsigned*)(cb + ph1 + colo);
                    unsigned y1b = *(const unsigned*)(cb + ph1 + colo + 4);
                    uint4 af = *(const uint4*)(ab + w * 128 + lane * 4);
                    mma_tf32(acc2[0], af, y0a, y1a);
                    mma_tf32(acc2[1], af, y0b, y1b);
                }
                // peephole part for step t+1 (tile 2 x cy)
#pragma unroll
                for (int q = 0; q < 2; q++) {
                    const int kt = kw * 2 + q, colo = kt * 8;
                    unsigned c0a = *(const unsigned*)(cb + brow0_2 + colo);
                    unsigned c1a = *(const unsigned*)(cb + brow0_2 + colo + 4);
                    unsigned c0b = *(const unsigned*)(cb + brow1_2 + colo);
                    unsigned c1b = *(const unsigned*)(cb + brow1_2 + colo + 4);
                    uint4 a2 = *(const uint4*)(sW + 32768 + (j * 8 + kt) * 128 + lane * 4);
                    mma_tf32(accp[0], a2, c0a, c1a);
                    mma_tf32(accp[1], a2, c0b, c1b);
                }
                __syncthreads();
            }

            // reductions: Wcyo over 8 warps, peephole over 4 kw-groups
            if (w > 0) {
                float* dst = sRedW + ((w - 1) * 32 + lane) * 8;
#pragma unroll
                for (int g = 0; g < 2; g++)
#pragma unroll
                    for (int j = 0; j < 4; j++) dst[g * 4 + j] = acc2[g][j];
            }
            if (kw > 0) {
                float* dst = sRedC + (((kw - 1) * 2 + bgset) * 32 + lane) * 8;
#pragma unroll
                for (int g = 0; g < 2; g++)
#pragma unroll
                    for (int j = 0; j < 4; j++) dst[g * 4 + j] = accp[g][j];
            }
            __syncthreads();
            if (w == 0) {
#pragma unroll
                for (int r = 0; r < 7; r++) {
                    const float* sp = sRedW + (r * 32 + lane) * 8;
#pragma unroll
                    for (int g = 0; g < 2; g++)
#pragma unroll
                        for (int j = 0; j < 4; j++) acc2[g][j] += sp[g * 4 + j];
                }
#pragma unroll
                for (int g = 0; g < 2; g++)
#pragma unroll
                    for (int j = 0; j < 4; j++) {
                        int row = ng * 16 + (lane >> 2) + 8 * (j >> 1);
                        int bcol = half * 16 + g * 8 + 2 * (lane & 3) + (j & 1);
                        int off = bcol * HH + row;
                        float o = 1.f / (1.f + expf(-(ppo[g][j] + acc2[g][j])));
                        float hy = o * tanhf(pcy[g][j]);
                        g_h[off] = hy;
                        out[(size_t)t * BH + off] = hy;
                    }
            }
            if (kw == 0) {
#pragma unroll
                for (int g = 0; g < 2; g++)
#pragma unroll
                    for (int j = 0; j < 4; j++) accC[g][j] = accp[g][j];
#pragma unroll
                for (int r = 0; r < 3; r++) {
                    const float* sp = sRedC + ((r * 2 + bgset) * 32 + lane) * 8;
#pragma unroll
                    for (int g = 0; g < 2; g++)
#pragma unroll
                        for (int j = 0; j < 4; j++) accC[g][j] += sp[g * 4 + j];
                }
            }
        }
        // barrier C (h published)
        bar_arrive(g_fC, bId, (unsigned)(t + 1));
        if (bId == 0) bar_master(g_fC, 128, (unsigned)(t + 1), &g_genC);
        else          bar_spin(&g_genC, (unsigned)(t + 1));
    }
}

extern "C" void kernel_launch(void* const* d_in, const int* in_sizes, int n_in,
                              void* d_out, int out_size)
{
    const float* X     = (const float*)d_in[0];
    const float* h0    = (const float*)d_in[1];
    const float* c0    = (const float*)d_in[2];
    const float* w_ii  = (const float*)d_in[3];
    const float* w_hi  = (const float*)d_in[4];
    const float* w_ci  = (const float*)d_in[5];
    const float* w_if  = (const float*)d_in[6];
    const float* w_hf  = (const float*)d_in[7];
    const float* w_cf  = (const float*)d_in[8];
    const float* w_ic  = (const float*)d_in[9];
    const float* w_hc  = (const float*)d_in[10];
    const float* w_io  = (const float*)d_in[11];
    const float* w_ho  = (const float*)d_in[12];
    const float* w_cyo = (const float*)d_in[13];
    float* out = (float*)d_out;

    cudaFuncSetAttribute(lstm_kernel,
                         cudaFuncAttributeMaxDynamicSharedMemorySize,
                         SMEM_FLOATS * 4);
    cudaFuncSetAttribute(proj2_kernel,
                         cudaFuncAttributeMaxDynamicSharedMemorySize,
                         PROJ_SMEM * 4);

    init_kernel<<<128, 256>>>(h0, c0,
        (const float*)d_in[14], (const float*)d_in[15], (const float*)d_in[16],
        (const float*)d_in[17], (const float*)d_in[18], (const float*)d_in[19],
        (const float*)d_in[20], (const float*)d_in[21], (const float*)d_in[22],
        (const float*)d_in[23], (const float*)d_in[24]);
    pack_kernel<<<28672, 256>>>(w_hi, w_hf, w_hc, w_ho, w_ci, w_cf, w_cyo);
    pack_in_kernel<<<8192, 256>>>(w_ii, w_if, w_ic, w_io);
    proj2_kernel<<<128, 256, PROJ_SMEM * 4>>>(X);
    lstm_kernel<<<NBLK, 256, SMEM_FLOATS * 4>>>(out);
}